// round 12
// baseline (speedup 1.0000x reference)
#include <cuda_runtime.h>
#include <cstdint>

#define NT 60
#define ND 36
#define NL 10
#define NS 9
#define NO 8
#define MIN_ (NT*NL + NS) // 609
#define NBJ 16384
#define ROWS ((size_t)NBJ * NT)   // 983040

typedef unsigned long long u64;

// 126 MB scratch; per (b,t) row of 32 floats, layout:
//   [au0-4, ar0-4, an0-4, pad | au5-9, ar5-9, an5-9, pad]  (au/ar pre-scaled by L2E)
__device__ __align__(128) float g_pre[ROWS * 32];

__device__ __forceinline__ float ex2(float x) {
    float r; asm("ex2.approx.ftz.f32 %0, %1;" : "=f"(r) : "f"(x)); return r;
}
__device__ __forceinline__ float frcp(float x) {
    float r; asm("rcp.approx.ftz.f32 %0, %1;" : "=f"(r) : "f"(x)); return r;
}
__device__ __forceinline__ void ffma2(u64& d, u64 a, u64 b) {
    asm("fma.rn.f32x2 %0, %1, %2, %0;" : "+l"(d) : "l"(a), "l"(b));
}
__device__ __forceinline__ u64 pack2(float v) {
    u64 r; asm("mov.b64 %0, {%1, %1};" : "=l"(r) : "f"(v)); return r;
}
__device__ __forceinline__ float2 unpack2(u64 v) {
    float2 f; asm("mov.b64 {%0, %1}, %2;" : "=f"(f.x), "=f"(f.y) : "l"(v)); return f;
}
__device__ __forceinline__ uint32_t smem_u32(const void* p) {
    return (uint32_t)__cvta_generic_to_shared(p);
}
__device__ __forceinline__ void cpasync16(uint32_t dst, const float* src) {
    asm volatile("cp.async.cg.shared.global [%0], [%1], 16;" :: "r"(dst), "l"(src));
}
__device__ __forceinline__ void cpcommit() {
    asm volatile("cp.async.commit_group;" ::: "memory");
}
template<int N> __device__ __forceinline__ void cpwait() {
    asm volatile("cp.async.wait_group %0;" :: "n"(N) : "memory");
}
__device__ __forceinline__ void barpair(int id) {
    asm volatile("bar.sync %0, 64;" :: "r"(id) : "memory");
}

// ============================================================================
// Kernel A: pre-activation GEMM (2 rows/thread, permuted half-block output)
// ============================================================================
__global__ __launch_bounds__(128) void preact_kernel(
    const float* __restrict__ data,
    const float* __restrict__ gWu, const float* __restrict__ gbu,
    const float* __restrict__ gWr, const float* __restrict__ gbr,
    const float* __restrict__ gWn, const float* __restrict__ gbn)
{
    __shared__ __align__(16) float W[ND][32];      // [k][u(10) r(10) n(10) pad2]
    __shared__ __align__(16) float bias[32];
    __shared__ __align__(16) float buf[256 * 37];  // in: 256 rows pad-37; out: pad-33
    const int tid = threadIdx.x;
    const float L2E = 1.4426950408889634f;

    for (int i = tid; i < ND * NL; i += 128) {
        int k = i / NL, j = i - k * NL;
        W[k][j]      = gWu[(NL + k) * NL + j] * L2E;
        W[k][10 + j] = gWr[(NL + k) * NL + j] * L2E;
        W[k][20 + j] = gWn[(NL + k) * NL + j];
    }
    for (int i = tid; i < ND * 2; i += 128) W[i / 2][30 + (i & 1)] = 0.f;
    if (tid < NL) {
        bias[tid]      = gbu[tid] * L2E;
        bias[10 + tid] = gbr[tid] * L2E;
        bias[20 + tid] = gbn[tid];
    }
    if (tid < 2) bias[30 + tid] = 0.f;

    // coalesced load of 256 rows (36 KB) into padded smem
    const size_t fbase = (size_t)blockIdx.x * 256 * ND;
    const float4* src4 = reinterpret_cast<const float4*>(data + fbase);
#pragma unroll
    for (int i = 0; i < 18; i++) {
        float4 v = src4[tid + 128 * i];
        int g = 4 * (tid + 128 * i);
        float vv[4] = {v.x, v.y, v.z, v.w};
#pragma unroll
        for (int j = 0; j < 4; j++) {
            int gg = g + j;
            buf[gg + gg / ND] = vv[j];
        }
    }
    __syncthreads();

    const float* x0 = buf + tid * 37;
    const float* x1 = buf + (tid + 128) * 37;
    u64 a0[15], a1[15];
    const u64* bp = (const u64*)bias;
#pragma unroll
    for (int p = 0; p < 15; p++) { a0[p] = bp[p]; a1[p] = bp[p]; }

#pragma unroll 6
    for (int k = 0; k < ND; k++) {
        u64 xp0 = pack2(x0[k]);
        u64 xp1 = pack2(x1[k]);
        const ulonglong2* w2 = (const ulonglong2*)W[k];
        ulonglong2 wa = w2[0], wb = w2[1], wc = w2[2];
        ulonglong2 wd = w2[3], we_ = w2[4], wf = w2[5], wg = w2[6];
        u64 w14 = ((const u64*)W[k])[14];
        ffma2(a0[0],  xp0, wa.x);  ffma2(a1[0],  xp1, wa.x);
        ffma2(a0[1],  xp0, wa.y);  ffma2(a1[1],  xp1, wa.y);
        ffma2(a0[2],  xp0, wb.x);  ffma2(a1[2],  xp1, wb.x);
        ffma2(a0[3],  xp0, wb.y);  ffma2(a1[3],  xp1, wb.y);
        ffma2(a0[4],  xp0, wc.x);  ffma2(a1[4],  xp1, wc.x);
        ffma2(a0[5],  xp0, wc.y);  ffma2(a1[5],  xp1, wc.y);
        ffma2(a0[6],  xp0, wd.x);  ffma2(a1[6],  xp1, wd.x);
        ffma2(a0[7],  xp0, wd.y);  ffma2(a1[7],  xp1, wd.y);
        ffma2(a0[8],  xp0, we_.x); ffma2(a1[8],  xp1, we_.x);
        ffma2(a0[9],  xp0, we_.y); ffma2(a1[9],  xp1, we_.y);
        ffma2(a0[10], xp0, wf.x);  ffma2(a1[10], xp1, wf.x);
        ffma2(a0[11], xp0, wf.y);  ffma2(a1[11], xp1, wf.y);
        ffma2(a0[12], xp0, wg.x);  ffma2(a1[12], xp1, wg.x);
        ffma2(a0[13], xp0, wg.y);  ffma2(a1[13], xp1, wg.y);
        ffma2(a0[14], xp0, w14);   ffma2(a1[14], xp1, w14);
    }
    __syncthreads();

    // permuted write: value for (gate gi, out j) -> pos (j/5)*16 + gi*5 + j%5
    float* o0 = buf + tid * 33;
    float* o1 = buf + (tid + 128) * 33;
#pragma unroll
    for (int gi = 0; gi < 3; gi++) {
#pragma unroll
        for (int p = 0; p < 5; p++) {
            float2 f0 = unpack2(a0[gi * 5 + p]);
            float2 f1 = unpack2(a1[gi * 5 + p]);
            const int j0 = 2 * p, j1 = 2 * p + 1;
            const int q0 = (j0 / 5) * 16 + gi * 5 + (j0 % 5);
            const int q1 = (j1 / 5) * 16 + gi * 5 + (j1 % 5);
            o0[q0] = f0.x; o0[q1] = f0.y;
            o1[q0] = f1.x; o1[q1] = f1.y;
        }
    }
    o0[15] = 0.f; o0[31] = 0.f;
    o1[15] = 0.f; o1[31] = 0.f;
    __syncthreads();

    float4* dst4 = reinterpret_cast<float4*>(g_pre + (size_t)blockIdx.x * 256 * 32);
#pragma unroll
    for (int i = 0; i < 16; i++) {
        int g4 = tid + 128 * i;
        int rl = g4 >> 3, q = g4 & 7;
        const float* s = buf + rl * 33 + q * 4;
        dst4[g4] = make_float4(s[0], s[1], s[2], s[3]);
    }
}

// ============================================================================
// Kernel B: recurrent scan, trajectory split across a WARP PAIR by outputs.
//   128 threads = 64 trajectories; thread (g, h) owns outputs [5h, 5h+5).
// ============================================================================
__global__ __launch_bounds__(128) void dgm2_kernel(
    const float* __restrict__ ts,
    const float* __restrict__ stat,
    const float* __restrict__ gWu,
    const float* __restrict__ gWr,
    const float* __restrict__ gWn,
    const float* __restrict__ gWo, const float* __restrict__ gbo,
    const float* __restrict__ gWm, const float* __restrict__ gbm,
    float* __restrict__ out)
{
    __shared__ __align__(16) float WO2[2][10][8];    // [h][k][own5 + pad3], x2*L2E
    __shared__ __align__(16) float WUR[2][10][12];   // [h][k][Wu own5, Wr own5, pad2], xL2E
    __shared__ __align__(16) float WN2[2][10][8];    // [h][k][own5 + pad3]
    __shared__ __align__(16) float Wm[MIN_][NO];
    __shared__ __align__(16) float bo2[2][8];        // x2*L2E
    __shared__ float bmS[NO];
    __shared__ float dts[NT];
    __shared__ __align__(16) float pre[2][8][64][4]; // [buf][chunk][traj][4]
    __shared__ float exYO[64][11];
    __shared__ float exR[64][11];
    __shared__ float exYN[64][11];

    const int tid = threadIdx.x;
    const float L2E = 1.4426950408889634f;

    // zero padded weight arrays, then fill
    for (int i = tid; i < 2 * 10 * 8; i += 128)  ((float*)WO2)[i] = 0.f;
    for (int i = tid; i < 2 * 10 * 12; i += 128) ((float*)WUR)[i] = 0.f;
    for (int i = tid; i < 2 * 10 * 8; i += 128)  ((float*)WN2)[i] = 0.f;
    if (tid < 16) ((float*)bo2)[tid] = 0.f;
    __syncthreads();
    for (int i = tid; i < 100; i += 128) {
        int k = i / 10, j = i % 10, hh = j / 5, c = j % 5;
        WO2[hh][k][c]     = gWo[k * NL + j] * (2.f * L2E);
        WUR[hh][k][c]     = gWu[k * NL + j] * L2E;   // yo-part rows (first 10)
        WUR[hh][k][5 + c] = gWr[k * NL + j] * L2E;
        WN2[hh][k][c]     = gWn[k * NL + j];
    }
    if (tid < NL) bo2[tid / 5][tid % 5] = gbo[tid] * (2.f * L2E);
    for (int i = tid; i < MIN_ * NO; i += 128) (&Wm[0][0])[i] = gWm[i];
    if (tid < NO) bmS[tid] = gbm[tid];
    for (int i = tid; i < NT; i += 128)
        dts[i] = (i == 0) ? 0.01f : (ts[i] - ts[i - 1]);
    __syncthreads();

    const int g = tid & 63;
    const int h = tid >> 6;
    const int bid = 1 + ((tid >> 5) & 1);      // pair barrier id: {w0,w2}=1, {w1,w3}=2
    const int b = blockIdx.x * 64 + g;
    const float* pg = g_pre + (size_t)b * NT * 32;

    u64 bo_r[3];
    bo_r[0] = ((const u64*)bo2[h])[0];
    bo_r[1] = ((const u64*)bo2[h])[1];
    bo_r[2] = ((const u64*)bo2[h])[2];

    // prefetch t=0 (each half loads its own 4 chunks)
#pragma unroll
    for (int c = 0; c < 4; c++)
        cpasync16(smem_u32(&pre[0][h * 4 + c][g][0]), pg + (h * 4 + c) * 4);
    cpcommit();

    float y[NL];
    u64 acc2[4];
#pragma unroll
    for (int j = 0; j < NL; j++) y[j] = 0.f;
#pragma unroll
    for (int o = 0; o < 4; o++) acc2[o] = 0ull;

#pragma unroll 1
    for (int t = 0; t < NT; t++) {
        if (t + 1 < NT) {
            const int nb = (t + 1) & 1;
            const float* src = pg + (size_t)(t + 1) * 32;
#pragma unroll
            for (int c = 0; c < 4; c++)
                cpasync16(smem_u32(&pre[nb][h * 4 + c][g][0]), src + (h * 4 + c) * 4);
            cpcommit();
        }
        const float dt = dts[t];
        const float dt2 = 2.f * dt;

        // ---- ODE partial: own 5 outputs over all 10 k ----
        u64 ynp[NL];
#pragma unroll
        for (int k = 0; k < NL; k++) ynp[k] = pack2(y[k]);
        u64 og[3] = {bo_r[0], bo_r[1], bo_r[2]};
#pragma unroll
        for (int k = 0; k < NL; k++) {
            const float* row = &WO2[h][k][0];
            ulonglong2 w01 = *(const ulonglong2*)row;
            u64 w2 = ((const u64*)row)[2];
            ffma2(og[0], ynp[k], w01.x);
            ffma2(og[1], ynp[k], w01.y);
            ffma2(og[2], ynp[k], w2);
        }
        float yo_own[5];
        {
            float2 f0 = unpack2(og[0]), f1 = unpack2(og[1]), f2 = unpack2(og[2]);
            float gv[5] = {f0.x, f0.y, f1.x, f1.y, f2.x};
#pragma unroll
            for (int i = 0; i < 5; i++)
                yo_own[i] = (y[h * 5 + i] + dt) - dt2 * frcp(ex2(gv[i]) + 1.f);
        }
        // X1: exchange yo
#pragma unroll
        for (int i = 0; i < 5; i++) exYO[g][h * 5 + i] = yo_own[i];
        barpair(bid);
        float yof[NL];
#pragma unroll
        for (int k = 0; k < NL; k++) yof[k] = exYO[g][k];

        // pre-activations for this step
        if (t + 1 < NT) cpwait<1>(); else cpwait<0>();
        u64 pv[8];
        const int cb = t & 1;
#pragma unroll
        for (int c = 0; c < 4; c++) {
            ulonglong2 v = *(const ulonglong2*)&pre[cb][h * 4 + c][g][0];
            pv[2 * c] = v.x; pv[2 * c + 1] = v.y;
        }

        // ---- gates (u,r) own 5 each, fused accumulator [au(5) ar(5)] ----
        u64 g5[5] = {pv[0], pv[1], pv[2], pv[3], pv[4]};
        u64 yop[NL];
#pragma unroll
        for (int k = 0; k < NL; k++) yop[k] = pack2(yof[k]);
#pragma unroll
        for (int k = 0; k < NL; k++) {
            const float* row = &WUR[h][k][0];
            ulonglong2 wa = ((const ulonglong2*)row)[0];
            ulonglong2 wb = ((const ulonglong2*)row)[1];
            u64 wc = ((const u64*)row)[4];
            ffma2(g5[0], yop[k], wa.x);
            ffma2(g5[1], yop[k], wa.y);
            ffma2(g5[2], yop[k], wb.x);
            ffma2(g5[3], yop[k], wb.y);
            ffma2(g5[4], yop[k], wc);
        }
        float u_own[5], r_own[5];
        {
            float2 f0 = unpack2(g5[0]), f1 = unpack2(g5[1]), f2 = unpack2(g5[2]);
            float2 f3 = unpack2(g5[3]), f4 = unpack2(g5[4]);
            float au[5] = {f0.x, f0.y, f1.x, f1.y, f2.x};
            float ar[5] = {f2.y, f3.x, f3.y, f4.x, f4.y};
#pragma unroll
            for (int i = 0; i < 5; i++) {
                u_own[i] = frcp(1.f + ex2(-au[i]));
                r_own[i] = frcp(1.f + ex2(-ar[i]));
            }
        }
        // X2: exchange r
#pragma unroll
        for (int i = 0; i < 5; i++) exR[g][h * 5 + i] = r_own[i];
        barpair(bid);
        float rf[NL];
#pragma unroll
        for (int k = 0; k < NL; k++) rf[k] = exR[g][k];

        // ---- candidate: own 5 outputs, input (yo*r) over all k ----
        u64 an3[3] = {pv[5], pv[6], pv[7]};
#pragma unroll
        for (int k = 0; k < NL; k++) {
            u64 cp = pack2(yof[k] * rf[k]);
            const float* row = &WN2[h][k][0];
            ulonglong2 w01 = *(const ulonglong2*)row;
            u64 w2 = ((const u64*)row)[2];
            ffma2(an3[0], cp, w01.x);
            ffma2(an3[1], cp, w01.y);
            ffma2(an3[2], cp, w2);
        }
        float yn_own[5];
        {
            float2 f0 = unpack2(an3[0]), f1 = unpack2(an3[1]), f2 = unpack2(an3[2]);
            float an[5] = {f0.x, f0.y, f1.x, f1.y, f2.x};
#pragma unroll
            for (int i = 0; i < 5; i++)
                yn_own[i] = an[i] + u_own[i] * (yo_own[i] - an[i]);
        }
        // X3: exchange yn -> full carried y
#pragma unroll
        for (int i = 0; i < 5; i++) exYN[g][h * 5 + i] = yn_own[i];
        barpair(bid);
#pragma unroll
        for (int k = 0; k < NL; k++) y[k] = exYN[g][k];

        // ---- fused MLP accumulation: own 5 l's ----
#pragma unroll
        for (int i = 0; i < 5; i++) {
            const float* wm = &Wm[t * NL + h * 5 + i][0];
            ulonglong2 w01 = ((const ulonglong2*)wm)[0];
            ulonglong2 w23 = ((const ulonglong2*)wm)[1];
            u64 yv = pack2(yn_own[i]);
            ffma2(acc2[0], yv, w01.x);
            ffma2(acc2[1], yv, w01.y);
            ffma2(acc2[2], yv, w23.x);
            ffma2(acc2[3], yv, w23.y);
        }
    }

    // ---- static part: split 5/4 across the pair ----
    const float* sp = stat + (size_t)b * NS;
#pragma unroll
    for (int i = 0; i < 5; i++) {
        int s = h * 5 + i;
        if (s < NS) {
            u64 sv = pack2(sp[s]);
            const float* wm = &Wm[NT * NL + s][0];
            ulonglong2 w01 = ((const ulonglong2*)wm)[0];
            ulonglong2 w23 = ((const ulonglong2*)wm)[1];
            ffma2(acc2[0], sv, w01.x);
            ffma2(acc2[1], sv, w01.y);
            ffma2(acc2[2], sv, w23.x);
            ffma2(acc2[3], sv, w23.y);
        }
    }
    // combine pair halves via smem (reuse exYO)
    if (h == 1) {
#pragma unroll
        for (int o = 0; o < 4; o++) {
            float2 f = unpack2(acc2[o]);
            exYO[g][2 * o] = f.x;
            exYO[g][2 * o + 1] = f.y;
        }
    }
    barpair(bid);
    if (h == 0) {
        float4 o0, o1;
        float2 f0 = unpack2(acc2[0]), f1 = unpack2(acc2[1]);
        float2 f2 = unpack2(acc2[2]), f3 = unpack2(acc2[3]);
        o0.x = f0.x + exYO[g][0] + bmS[0];
        o0.y = f0.y + exYO[g][1] + bmS[1];
        o0.z = f1.x + exYO[g][2] + bmS[2];
        o0.w = f1.y + exYO[g][3] + bmS[3];
        o1.x = f2.x + exYO[g][4] + bmS[4];
        o1.y = f2.y + exYO[g][5] + bmS[5];
        o1.z = f3.x + exYO[g][6] + bmS[6];
        o1.w = f3.y + exYO[g][7] + bmS[7];
        float4* op = reinterpret_cast<float4*>(out + (size_t)b * NO);
        op[0] = o0;
        op[1] = o1;
    }
}

extern "C" void kernel_launch(void* const* d_in, const int* in_sizes, int n_in,
                              void* d_out, int out_size) {
    // Phase A: pre-activation GEMM (256 rows/block, 2 rows/thread)
    preact_kernel<<<(int)(ROWS / 256), 128>>>(
        (const float*)d_in[0],                            // data
        (const float*)d_in[3], (const float*)d_in[4],     // W_update, b_update
        (const float*)d_in[5], (const float*)d_in[6],     // W_reset,  b_reset
        (const float*)d_in[7], (const float*)d_in[8]);    // W_new,    b_new
    // Phase B: recurrent scan, warp-pair split (W_emit/b_emit are dead code)
    dgm2_kernel<<<NBJ / 64, 128>>>(
        (const float*)d_in[1],                            // time_steps
        (const float*)d_in[2],                            // static_data
        (const float*)d_in[3],                            // W_update (yo rows)
        (const float*)d_in[5],                            // W_reset  (yo rows)
        (const float*)d_in[7],                            // W_new    (cand rows)
        (const float*)d_in[11], (const float*)d_in[12],   // W_ode, b_ode
        (const float*)d_in[13], (const float*)d_in[14],   // W_mlp, b_mlp
        (float*)d_out);
}